// round 15
// baseline (speedup 1.0000x reference)
#include <cuda_runtime.h>
#include <cuda_fp16.h>
#include <cstdint>

#define ROI_SCALE 0.125f

// ---------------- scratch (device globals; no allocation allowed) ----------------
__device__ __half g_zt [8ul*64*64*1280]; // NHWC fp16 transpose of z
__device__ __half g_X  [1024ul*1280];    // roi output (fp16)
__device__ __half g_H  [1024ul*5120];    // fp16 activations
__device__ __half g_CAT[1024ul*2048];    // fp16 concat
__device__ __half g_E2 [1024ul*256];     // bbox-MLP layer-2 output (fp16)
__device__ __half g_W1t[5120ul*1280];    // N-major fp16 weights
__device__ __half g_W2t[1024ul*5120];
__device__ __half g_Ot [1024ul*2048];
__device__ __half g_S3t[1024ul*256];     // N-major fp16 S3
__device__ float g_P [6ul*1024*1024];    // split-K fp32 partials (GEMM2/3 + bbox path)

// ---------------- helpers ----------------
__device__ __forceinline__ void cpasync16(uint32_t saddr, const void* gaddr) {
    asm volatile("cp.async.cg.shared.global [%0], [%1], 16;\n" :: "r"(saddr), "l"(gaddr));
}

__device__ __forceinline__ void ldsm4(uint32_t* r, uint32_t a) {
    asm volatile("ldmatrix.sync.aligned.m8n8.x4.shared.b16 {%0,%1,%2,%3}, [%4];"
                 : "=r"(r[0]), "=r"(r[1]), "=r"(r[2]), "=r"(r[3]) : "r"(a));
}

__device__ __forceinline__ void mma16816(float* c, const uint32_t* a, const uint32_t* b) {
    asm volatile(
        "mma.sync.aligned.m16n8k16.row.col.f32.f16.f16.f32 "
        "{%0,%1,%2,%3},{%4,%5,%6,%7},{%8,%9},{%0,%1,%2,%3};"
        : "+f"(c[0]), "+f"(c[1]), "+f"(c[2]), "+f"(c[3])
        : "r"(a[0]), "r"(a[1]), "r"(a[2]), "r"(a[3]), "r"(b[0]), "r"(b[1]));
}

// ---------------- 1) transpose z (batch range): NCHW f32 -> NHWC fp16 ----------------
__global__ void transpose_kernel(const float* __restrict__ z, int b0)
{
    __shared__ float tile[64][33];
    const int b  = b0 + blockIdx.z;
    const int p0 = blockIdx.x * 32;   // pixel tile
    const int c0 = blockIdx.y * 64;   // channel tile
    const float* src = z    + (size_t)b * 1280 * 4096;
    __half*      dst = g_zt + (size_t)b * 4096 * 1280;
    const int tx = threadIdx.x, ty = threadIdx.y;
    #pragma unroll
    for (int i = 0; i < 8; i++)
        tile[ty + i*8][tx] = src[(size_t)(c0 + ty + i*8) * 4096 + p0 + tx];
    __syncthreads();
    #pragma unroll
    for (int i = 0; i < 4; i++) {
        const int pr = ty + i*8;
        __half2 h = __floats2half2_rn(tile[2*tx][pr], tile[2*tx + 1][pr]);
        *(__half2*)(dst + (size_t)(p0 + pr) * 1280 + c0 + 2*tx) = h;
    }
}

// ---------------- 1b) weight convert + transpose: W[K][N] f32 -> Wt[N][K] fp16 ----
__global__ void convt_kernel(const float* __restrict__ W,
                             __half* __restrict__ T, int K, int N)
{
    __shared__ float tile[32][33];
    const int n0 = blockIdx.x * 32;
    const int k0 = blockIdx.y * 32;
    const int tx = threadIdx.x, ty = threadIdx.y;
    #pragma unroll
    for (int i = 0; i < 4; i++)
        tile[ty + i*8][tx] = W[(size_t)(k0 + ty + i*8) * N + n0 + tx];
    __syncthreads();
    #pragma unroll
    for (int i = 0; i < 4; i++) {
        float v = tile[tx][ty + i*8];
        T[(size_t)(n0 + ty + i*8) * K + k0 + tx] = __float2half_rn(v);
    }
}

// ---------------- 2) RoIAlign 1x1, separable weights, uint2 (4-ch) vector reads ----
__global__ __launch_bounds__(320)
void roi_align_kernel(const float* __restrict__ bboxes, int rbase)
{
    __shared__ int   syi[18], sxi[18];
    __shared__ float syw[18], sxw[18];
    __shared__ int   sny, snx;
    __shared__ float sinv;

    const int r   = rbase + blockIdx.x;
    const int tid = threadIdx.x;      // 0..319, owns channels 4*tid..4*tid+3

    if (tid == 0) {
        const float* bb = bboxes + (size_t)r * 4;
        float x1 = bb[0]*ROI_SCALE - 0.5f, y1 = bb[1]*ROI_SCALE - 0.5f;
        float x2 = bb[2]*ROI_SCALE - 0.5f, y2 = bb[3]*ROI_SCALE - 0.5f;
        float rw = x2 - x1, rh = y2 - y1;
        float gwf = fminf(fmaxf(ceilf(rw), 1.f), 8.f);
        float ghf = fminf(fmaxf(ceilf(rh), 1.f), 8.f);
        int gh = (int)ghf, gw = (int)gwf;
        sinv = 1.f / (ghf * gwf);

        float W[64];
        for (int j = 0; j < 64; j++) W[j] = 0.f;
        for (int i = 0; i < gh; i++) {
            float ys = y1 + ((float)i + 0.5f) * rh / ghf;
            if (ys < -1.f || ys > 64.f) continue;
            float cy = fmaxf(ys, 0.f);
            float l0 = floorf(cy);
            int yl = (int)fminf(l0, 63.f);
            int yh = (int)fminf(l0 + 1.f, 63.f);
            float fy = (l0 >= 63.f) ? 0.f : (cy - l0);
            W[yl] += 1.f - fy;
            W[yh] += fy;
        }
        int n = 0;
        for (int j = 0; j < 64; j++)
            if (W[j] != 0.f) { syi[n] = j; syw[n] = W[j]; n++; }
        sny = n;
        for (int j = 0; j < 64; j++) W[j] = 0.f;
        for (int i = 0; i < gw; i++) {
            float xs = x1 + ((float)i + 0.5f) * rw / gwf;
            if (xs < -1.f || xs > 64.f) continue;
            float cx = fmaxf(xs, 0.f);
            float l0 = floorf(cx);
            int xl = (int)fminf(l0, 63.f);
            int xh = (int)fminf(l0 + 1.f, 63.f);
            float fx = (l0 >= 63.f) ? 0.f : (cx - l0);
            W[xl] += 1.f - fx;
            W[xh] += fx;
        }
        n = 0;
        for (int j = 0; j < 64; j++)
            if (W[j] != 0.f) { sxi[n] = j; sxw[n] = W[j]; n++; }
        snx = n;
    }
    __syncthreads();

    const int b = r >> 7;
    const __half* base = g_zt + (size_t)b * 4096 * 1280 + tid * 4;
    float a0 = 0.f, a1 = 0.f, a2 = 0.f, a3 = 0.f;

    const int NY = sny, NX = snx;
    for (int iy = 0; iy < NY; iy++) {
        const __half* py = base + (size_t)syi[iy] * (64 * 1280);
        float t0 = 0.f, t1 = 0.f, t2 = 0.f, t3 = 0.f;
        for (int ix = 0; ix < NX; ix++) {
            uint2 v = *(const uint2*)(py + (size_t)sxi[ix] * 1280);
            float2 lo = __half22float2(*(const __half2*)&v.x);
            float2 hi = __half22float2(*(const __half2*)&v.y);
            const float w = sxw[ix];
            t0 += w * lo.x; t1 += w * lo.y;
            t2 += w * hi.x; t3 += w * hi.y;
        }
        const float wy = syw[iy];
        a0 += wy * t0; a1 += wy * t1; a2 += wy * t2; a3 += wy * t3;
    }
    __half2 o0 = __floats2half2_rn(a0 * sinv, a1 * sinv);
    __half2 o1 = __floats2half2_rn(a2 * sinv, a3 * sinv);
    uint2 packed;
    packed.x = *(const uint32_t*)&o0;
    packed.y = *(const uint32_t*)&o1;
    *(uint2*)(g_X + (size_t)r * 1280 + tid * 4) = packed;
}

// ---------------- 3) fp16 mma.sync GEMM ----------------
// OUT: 1 = fused bias+relu+fp16 store (no split-K), 3 = fp32 split-K partial
#define ROWB 80
#define GBM 128
#define NSTG 4

template<int OUT>
__global__ __launch_bounds__(256, 2)
void mma_gemm(const __half* __restrict__ Ah, const __half* __restrict__ Bh,
              const float* __restrict__ bias,
              float* __restrict__ P, __half* __restrict__ Ch,
              int K, int Klen, int N, int ldc)
{
    constexpr int BHOFF = GBM * ROWB;
    constexpr int STG   = (GBM + 128) * ROWB;    // 20480

    extern __shared__ char smem[];
    const uint32_t sb = (uint32_t)__cvta_generic_to_shared(smem);

    const int tid  = threadIdx.x;
    const int wid  = tid >> 5, lane = tid & 31;
    const int wm   = (wid >> 2) * 64;
    const int wn   = (wid & 3) * 32;
    const int qrow = lane >> 2, qcol = lane & 3;
    const int m0   = blockIdx.y * GBM;
    const int n0   = blockIdx.x * 128;
    const int koff = blockIdx.z * Klen;

    const uint32_t aoff = (uint32_t)((wm + (lane & 15)) * ROWB + (lane >> 4) * 16);
    const uint32_t boff = (uint32_t)((wn + ((lane >> 4) << 3) + (lane & 7)) * ROWB
                                     + ((lane >> 3) & 1) * 16);

    float acc[4][4][4];
    #pragma unroll
    for (int i = 0; i < 4; i++)
        #pragma unroll
        for (int j = 0; j < 4; j++)
            #pragma unroll
            for (int q = 0; q < 4; q++) acc[i][j][q] = 0.f;

    auto load_stage = [&](int st, int kc) {
        const uint32_t base = sb + st * STG;
        #pragma unroll
        for (int i = 0; i < 2; i++) {
            int f = tid + i * 256;
            int row = f >> 2, c = f & 3;
            size_t g = (size_t)(m0 + row) * K + koff + kc + c * 8;
            cpasync16(base + (uint32_t)(row * ROWB + c * 16), Ah + g);
        }
        #pragma unroll
        for (int i = 0; i < 2; i++) {
            int f = tid + i * 256;
            int row = f >> 2, c = f & 3;
            size_t g = (size_t)(n0 + row) * K + koff + kc + c * 8;
            cpasync16(base + BHOFF + (uint32_t)(row * ROWB + c * 16), Bh + g);
        }
        asm volatile("cp.async.commit_group;\n" ::: "memory");
    };

    const int S = Klen >> 5;
    load_stage(0, 0);
    load_stage(1, 32);
    load_stage(2, 64);

    for (int s = 0; s < S; s++) {
        const int rem = S - s - 1;
        if (rem >= 2)      asm volatile("cp.async.wait_group 2;\n" ::: "memory");
        else if (rem == 1) asm volatile("cp.async.wait_group 1;\n" ::: "memory");
        else               asm volatile("cp.async.wait_group 0;\n" ::: "memory");
        __syncthreads();
        if (s + 3 < S) load_stage((s + 3) % NSTG, (s + 3) * 32);

        const uint32_t base = sb + (s % NSTG) * STG;
        #pragma unroll
        for (int ks = 0; ks < 2; ks++) {
            uint32_t bh[2][4];
            #pragma unroll
            for (int p = 0; p < 2; p++)
                ldsm4(bh[p], base + BHOFF + boff + p * (16*ROWB) + ks * 32);
            #pragma unroll
            for (int mt = 0; mt < 4; mt++) {
                uint32_t ah[4];
                ldsm4(ah, base + aoff + mt * (16*ROWB) + ks * 32);
                #pragma unroll
                for (int nt = 0; nt < 4; nt++) {
                    const uint32_t* bp = &bh[nt >> 1][(nt & 1) * 2];
                    mma16816(acc[mt][nt], ah, bp);
                }
            }
        }
        // no trailing sync: top-of-step sync two steps later protects reuse (depth >= 3)
    }

    if (OUT == 3) {
        float* Pz = P + (size_t)blockIdx.z * 1024 * N;
        #pragma unroll
        for (int mt = 0; mt < 4; mt++) {
            int r0 = m0 + wm + mt * 16 + qrow;
            #pragma unroll
            for (int nt = 0; nt < 4; nt++) {
                int c = n0 + wn + nt * 8 + qcol * 2;
                size_t i0 = (size_t)r0 * N + c;
                size_t i1 = (size_t)(r0 + 8) * N + c;
                Pz[i0] = acc[mt][nt][0]; Pz[i0 + 1] = acc[mt][nt][1];
                Pz[i1] = acc[mt][nt][2]; Pz[i1 + 1] = acc[mt][nt][3];
            }
        }
    } else {
        #pragma unroll
        for (int mt = 0; mt < 4; mt++) {
            int r0 = m0 + wm + mt * 16 + qrow;
            #pragma unroll
            for (int nt = 0; nt < 4; nt++) {
                int c = n0 + wn + nt * 8 + qcol * 2;
                float bv0 = bias[c], bv1 = bias[c + 1];
                float v00 = fmaxf(acc[mt][nt][0] + bv0, 0.f);
                float v01 = fmaxf(acc[mt][nt][1] + bv1, 0.f);
                float v10 = fmaxf(acc[mt][nt][2] + bv0, 0.f);
                float v11 = fmaxf(acc[mt][nt][3] + bv1, 0.f);
                size_t i0 = (size_t)r0 * ldc + c;
                size_t i1 = (size_t)(r0 + 8) * ldc + c;
                *(__half2*)(Ch + i0) = __halves2half2(__float2half_rn(v00), __float2half_rn(v01));
                *(__half2*)(Ch + i1) = __halves2half2(__float2half_rn(v10), __float2half_rn(v11));
            }
        }
    }
}

// ---------------- 3b) split-K reduce, NSLAB partial slabs (+bias, optional relu) ----------------
// OUT: 0 = f32 to Cf, 2 = fp16 to Ch
template<int OUT, int NSLAB>
__global__ __launch_bounds__(256)
void reduce_k(const float* __restrict__ P, const float* __restrict__ bias,
              float* __restrict__ Cf, __half* __restrict__ Ch, int N, int ldc)
{
    const int idx = blockIdx.x * 256 + threadIdx.x;   // f4 index
    const int nq  = N >> 2;
    const int r   = idx / nq;
    const int c   = (idx % nq) * 4;
    const size_t p = (size_t)r * N + c;
    const size_t slab = (size_t)1024 * N;
    float4 a = *(const float4*)(P + p);
    float4 bv = *(const float4*)(bias + c);
    float v0 = a.x + bv.x, v1 = a.y + bv.y, v2 = a.z + bv.z, v3 = a.w + bv.w;
    #pragma unroll
    for (int zi = 1; zi < NSLAB; zi++) {
        float4 b = *(const float4*)(P + zi * slab + p);
        v0 += b.x; v1 += b.y; v2 += b.z; v3 += b.w;
    }
    if (OUT == 0) {
        *(float4*)(Cf + (size_t)r * ldc + c) = make_float4(v0, v1, v2, v3);
    } else {
        size_t o = (size_t)r * ldc + c;
        *(__half2*)(Ch + o)     = __halves2half2(__float2half_rn(v0), __float2half_rn(v1));
        *(__half2*)(Ch + o + 2) = __halves2half2(__float2half_rn(v2), __float2half_rn(v3));
    }
}

// ---------------- 4) bbox-size MLP layers 1+2 (parallel) ----------------
__global__ __launch_bounds__(256) void mlp12_kernel(
    const float* __restrict__ bboxes,
    const float* __restrict__ S1, const float* __restrict__ sb1,
    const float* __restrict__ S2, const float* __restrict__ sb2)
{
    __shared__ float e1[4][64];
    const int r0  = blockIdx.x * 4;
    const int tid = threadIdx.x;

    {
        const int row = tid >> 6, col = tid & 63;
        const float* bb = bboxes + (size_t)(r0 + row) * 4;
        float h = bb[3] - bb[1], w = bb[2] - bb[0];
        float v = h * S1[col] + w * S1[64 + col] + sb1[col];
        e1[row][col] = fmaxf(v, 0.f);
    }
    __syncthreads();

    float a[4];
    const float bv = sb2[tid];
    #pragma unroll
    for (int r = 0; r < 4; r++) a[r] = bv;
    #pragma unroll 8
    for (int k = 0; k < 64; k++) {
        const float s = S2[(size_t)k * 256 + tid];
        #pragma unroll
        for (int r = 0; r < 4; r++) a[r] += e1[r][k] * s;
    }
    #pragma unroll
    for (int r = 0; r < 4; r++)
        g_E2[(size_t)(r0 + r) * 256 + tid] = __float2half_rn(fmaxf(a[r], 0.f));
}

// ---------------- launch ----------------
extern "C" void kernel_launch(void* const* d_in, const int* in_sizes, int n_in,
                              void* d_out, int out_size)
{
    const float* z      = (const float*)d_in[0];
    const float* bboxes = (const float*)d_in[1];
    const float* W1     = (const float*)d_in[2];
    const float* b1     = (const float*)d_in[3];
    const float* W2     = (const float*)d_in[4];
    const float* b2     = (const float*)d_in[5];
    const float* S1     = (const float*)d_in[6];
    const float* sb1    = (const float*)d_in[7];
    const float* S2     = (const float*)d_in[8];
    const float* sb2    = (const float*)d_in[9];
    const float* S3     = (const float*)d_in[10];
    const float* sb3    = (const float*)d_in[11];
    const float* O      = (const float*)d_in[12];
    const float* ob     = (const float*)d_in[13];
    float* out = (float*)d_out;

    __half *X, *H, *CAT, *E2, *W1t, *W2t, *Ot, *S3t;
    float* P;
    cudaGetSymbolAddress((void**)&X,   g_X);
    cudaGetSymbolAddress((void**)&H,   g_H);
    cudaGetSymbolAddress((void**)&CAT, g_CAT);
    cudaGetSymbolAddress((void**)&E2,  g_E2);
    cudaGetSymbolAddress((void**)&W1t, g_W1t);
    cudaGetSymbolAddress((void**)&W2t, g_W2t);
    cudaGetSymbolAddress((void**)&Ot,  g_Ot);
    cudaGetSymbolAddress((void**)&S3t, g_S3t);
    cudaGetSymbolAddress((void**)&P,   g_P);

    constexpr int SMEM = (GBM + 128) * ROWB * NSTG;   // 81920

    static cudaStream_t s2 = nullptr, s3 = nullptr;
    static cudaEvent_t  eFork = nullptr, eJoin = nullptr, eRoi = nullptr;
    static cudaEvent_t  eT0 = nullptr, eT1 = nullptr;
    static bool init_done = false;
    if (!init_done) {
        cudaFuncSetAttribute((const void*)mma_gemm<1>, cudaFuncAttributeMaxDynamicSharedMemorySize, SMEM);
        cudaFuncSetAttribute((const void*)mma_gemm<3>, cudaFuncAttributeMaxDynamicSharedMemorySize, SMEM);
        cudaStreamCreateWithFlags(&s2, cudaStreamNonBlocking);
        cudaStreamCreateWithFlags(&s3, cudaStreamNonBlocking);
        cudaEventCreateWithFlags(&eFork, cudaEventDisableTiming);
        cudaEventCreateWithFlags(&eJoin, cudaEventDisableTiming);
        cudaEventCreateWithFlags(&eRoi,  cudaEventDisableTiming);
        cudaEventCreateWithFlags(&eT0,   cudaEventDisableTiming);
        cudaEventCreateWithFlags(&eT1,   cudaEventDisableTiming);
        init_done = true;
    }

    // ---- fork: independent preamble on s2 ----
    cudaEventRecord(eFork, 0);
    cudaStreamWaitEvent(s2, eFork, 0);
    cudaStreamWaitEvent(s3, eFork, 0);
    // bbox-MLP path: layers 1+2, then layer 3 via tensor-core GEMM
    convt_kernel<<<dim3(1024/32, 256/32), dim3(32, 8), 0, s2>>>(S3, S3t, 256, 1024);
    mlp12_kernel<<<256, 256, 0, s2>>>(bboxes, S1, sb1, S2, sb2);
    mma_gemm<3><<<dim3(1024/128, 1024/128, 2), 256, SMEM, s2>>>(
        E2, S3t, nullptr, P + 4ul*1024*1024, nullptr, 256, 128, 1024, 0);
    reduce_k<2,2><<<1024, 256, 0, s2>>>(P + 4ul*1024*1024, sb3, nullptr, CAT + 1024, 1024, 2048);
    // weight conversions
    convt_kernel<<<dim3(5120/32, 1280/32), dim3(32, 8), 0, s2>>>(W1, W1t, 1280, 5120);
    convt_kernel<<<dim3(1024/32, 5120/32), dim3(32, 8), 0, s2>>>(W2, W2t, 5120, 1024);
    convt_kernel<<<dim3(1024/32, 2048/32), dim3(32, 8), 0, s2>>>(O,  Ot,  2048, 1024);
    cudaEventRecord(eJoin, s2);

    // ---- main stream + s3: two-stage transpose -> roi pipeline ----
    transpose_kernel<<<dim3(128, 20, 4), dim3(32, 8)>>>(z, 0);
    cudaEventRecord(eT0, 0);
    transpose_kernel<<<dim3(128, 20, 4), dim3(32, 8)>>>(z, 4);
    cudaEventRecord(eT1, 0);
    cudaStreamWaitEvent(s3, eT0, 0);
    roi_align_kernel<<<512, 320, 0, s3>>>(bboxes, 0);
    cudaStreamWaitEvent(s3, eT1, 0);
    roi_align_kernel<<<512, 320, 0, s3>>>(bboxes, 512);
    cudaEventRecord(eRoi, s3);
    cudaStreamWaitEvent(0, eRoi, 0);

    // ---- join before GEMMs ----
    cudaStreamWaitEvent(0, eJoin, 0);

    // GEMM1: H = relu(X @ W1 + b1), fused epilogue, no split-K (320 blocks)
    mma_gemm<1><<<dim3(5120/128, 1024/128), 256, SMEM>>>(
        X, W1t, b1, nullptr, H, 1280, 1280, 5120, 5120);

    // GEMM2: P = H @ W2 (split-K 4x1280) -> CAT[:, :1024] = fp16(sum+b2)
    mma_gemm<3><<<dim3(1024/128, 1024/128, 4), 256, SMEM>>>(
        H, W2t, nullptr, P, nullptr, 5120, 1280, 1024, 0);
    reduce_k<2,4><<<1024, 256>>>(P, b2, nullptr, CAT, 1024, 2048);

    // GEMM3: P = CAT @ O (split-K 4x512) -> out = sum+ob, f32
    mma_gemm<3><<<dim3(1024/128, 1024/128, 4), 256, SMEM>>>(
        CAT, Ot, nullptr, P, nullptr, 2048, 512, 1024, 0);
    reduce_k<0,4><<<1024, 256>>>(P, ob, out, nullptr, 1024, 1024);
}

// round 16
// speedup vs baseline: 1.0298x; 1.0298x over previous
#include <cuda_runtime.h>
#include <cuda_fp16.h>
#include <cstdint>

#define ROI_SCALE 0.125f

// ---------------- scratch (device globals; no allocation allowed) ----------------
__device__ __half g_zt [8ul*64*64*1280]; // NHWC fp16 transpose of z
__device__ __half g_X  [1024ul*1280];    // roi output (fp16)
__device__ __half g_H  [1024ul*5120];    // fp16 activations
__device__ __half g_CAT[1024ul*2048];    // fp16 concat
__device__ __half g_E2 [1024ul*256];     // bbox-MLP layer-2 output (fp16)
__device__ __half g_W1t[5120ul*1280];    // N-major fp16 weights
__device__ __half g_W2t[1024ul*5120];
__device__ __half g_Ot [1024ul*2048];
__device__ __half g_S3t[1024ul*256];     // N-major fp16 S3
__device__ float g_P [6ul*1024*1024];    // split-K fp32 partials (GEMM2/3 + bbox path)

// ---------------- helpers ----------------
__device__ __forceinline__ void cpasync16(uint32_t saddr, const void* gaddr) {
    asm volatile("cp.async.cg.shared.global [%0], [%1], 16;\n" :: "r"(saddr), "l"(gaddr));
}

__device__ __forceinline__ void ldsm4(uint32_t* r, uint32_t a) {
    asm volatile("ldmatrix.sync.aligned.m8n8.x4.shared.b16 {%0,%1,%2,%3}, [%4];"
                 : "=r"(r[0]), "=r"(r[1]), "=r"(r[2]), "=r"(r[3]) : "r"(a));
}

__device__ __forceinline__ void mma16816(float* c, const uint32_t* a, const uint32_t* b) {
    asm volatile(
        "mma.sync.aligned.m16n8k16.row.col.f32.f16.f16.f32 "
        "{%0,%1,%2,%3},{%4,%5,%6,%7},{%8,%9},{%0,%1,%2,%3};"
        : "+f"(c[0]), "+f"(c[1]), "+f"(c[2]), "+f"(c[3])
        : "r"(a[0]), "r"(a[1]), "r"(a[2]), "r"(a[3]), "r"(b[0]), "r"(b[1]));
}

// ---------------- 1) transpose z: NCHW f32 -> NHWC fp16 (64-ch tiles, half2 stores) ----
__global__ void transpose_kernel(const float* __restrict__ z)
{
    __shared__ float tile[64][33];
    const int b  = blockIdx.z;
    const int p0 = blockIdx.x * 32;   // pixel tile
    const int c0 = blockIdx.y * 64;   // channel tile
    const float* src = z    + (size_t)b * 1280 * 4096;
    __half*      dst = g_zt + (size_t)b * 4096 * 1280;
    const int tx = threadIdx.x, ty = threadIdx.y;
    #pragma unroll
    for (int i = 0; i < 8; i++)
        tile[ty + i*8][tx] = src[(size_t)(c0 + ty + i*8) * 4096 + p0 + tx];
    __syncthreads();
    #pragma unroll
    for (int i = 0; i < 4; i++) {
        const int pr = ty + i*8;
        __half2 h = __floats2half2_rn(tile[2*tx][pr], tile[2*tx + 1][pr]);
        *(__half2*)(dst + (size_t)(p0 + pr) * 1280 + c0 + 2*tx) = h;
    }
}

// ---------------- 1b) weight convert + transpose: W[K][N] f32 -> Wt[N][K] fp16 ----
__global__ void convt_kernel(const float* __restrict__ W,
                             __half* __restrict__ T, int K, int N)
{
    __shared__ float tile[32][33];
    const int n0 = blockIdx.x * 32;
    const int k0 = blockIdx.y * 32;
    const int tx = threadIdx.x, ty = threadIdx.y;
    #pragma unroll
    for (int i = 0; i < 4; i++)
        tile[ty + i*8][tx] = W[(size_t)(k0 + ty + i*8) * N + n0 + tx];
    __syncthreads();
    #pragma unroll
    for (int i = 0; i < 4; i++) {
        float v = tile[tx][ty + i*8];
        T[(size_t)(n0 + ty + i*8) * K + k0 + tx] = __float2half_rn(v);
    }
}

// ---------------- 2) RoIAlign 1x1, separable weights, uint2 (4-ch) vector reads ----
__global__ __launch_bounds__(320)
void roi_align_kernel(const float* __restrict__ bboxes)
{
    __shared__ int   syi[18], sxi[18];
    __shared__ float syw[18], sxw[18];
    __shared__ int   sny, snx;
    __shared__ float sinv;

    const int r   = blockIdx.x;
    const int tid = threadIdx.x;      // 0..319, owns channels 4*tid..4*tid+3

    if (tid == 0) {
        const float* bb = bboxes + (size_t)r * 4;
        float x1 = bb[0]*ROI_SCALE - 0.5f, y1 = bb[1]*ROI_SCALE - 0.5f;
        float x2 = bb[2]*ROI_SCALE - 0.5f, y2 = bb[3]*ROI_SCALE - 0.5f;
        float rw = x2 - x1, rh = y2 - y1;
        float gwf = fminf(fmaxf(ceilf(rw), 1.f), 8.f);
        float ghf = fminf(fmaxf(ceilf(rh), 1.f), 8.f);
        int gh = (int)ghf, gw = (int)gwf;
        sinv = 1.f / (ghf * gwf);

        float W[64];
        for (int j = 0; j < 64; j++) W[j] = 0.f;
        for (int i = 0; i < gh; i++) {
            float ys = y1 + ((float)i + 0.5f) * rh / ghf;
            if (ys < -1.f || ys > 64.f) continue;
            float cy = fmaxf(ys, 0.f);
            float l0 = floorf(cy);
            int yl = (int)fminf(l0, 63.f);
            int yh = (int)fminf(l0 + 1.f, 63.f);
            float fy = (l0 >= 63.f) ? 0.f : (cy - l0);
            W[yl] += 1.f - fy;
            W[yh] += fy;
        }
        int n = 0;
        for (int j = 0; j < 64; j++)
            if (W[j] != 0.f) { syi[n] = j; syw[n] = W[j]; n++; }
        sny = n;
        for (int j = 0; j < 64; j++) W[j] = 0.f;
        for (int i = 0; i < gw; i++) {
            float xs = x1 + ((float)i + 0.5f) * rw / gwf;
            if (xs < -1.f || xs > 64.f) continue;
            float cx = fmaxf(xs, 0.f);
            float l0 = floorf(cx);
            int xl = (int)fminf(l0, 63.f);
            int xh = (int)fminf(l0 + 1.f, 63.f);
            float fx = (l0 >= 63.f) ? 0.f : (cx - l0);
            W[xl] += 1.f - fx;
            W[xh] += fx;
        }
        n = 0;
        for (int j = 0; j < 64; j++)
            if (W[j] != 0.f) { sxi[n] = j; sxw[n] = W[j]; n++; }
        snx = n;
    }
    __syncthreads();

    const int b = r >> 7;
    const __half* base = g_zt + (size_t)b * 4096 * 1280 + tid * 4;
    float a0 = 0.f, a1 = 0.f, a2 = 0.f, a3 = 0.f;

    const int NY = sny, NX = snx;
    for (int iy = 0; iy < NY; iy++) {
        const __half* py = base + (size_t)syi[iy] * (64 * 1280);
        float t0 = 0.f, t1 = 0.f, t2 = 0.f, t3 = 0.f;
        for (int ix = 0; ix < NX; ix++) {
            uint2 v = *(const uint2*)(py + (size_t)sxi[ix] * 1280);
            float2 lo = __half22float2(*(const __half2*)&v.x);
            float2 hi = __half22float2(*(const __half2*)&v.y);
            const float w = sxw[ix];
            t0 += w * lo.x; t1 += w * lo.y;
            t2 += w * hi.x; t3 += w * hi.y;
        }
        const float wy = syw[iy];
        a0 += wy * t0; a1 += wy * t1; a2 += wy * t2; a3 += wy * t3;
    }
    __half2 o0 = __floats2half2_rn(a0 * sinv, a1 * sinv);
    __half2 o1 = __floats2half2_rn(a2 * sinv, a3 * sinv);
    uint2 packed;
    packed.x = *(const uint32_t*)&o0;
    packed.y = *(const uint32_t*)&o1;
    *(uint2*)(g_X + (size_t)r * 1280 + tid * 4) = packed;
}

// ---------------- 3) fp16 mma.sync GEMM ----------------
// OUT: 1 = fused bias+relu+fp16 store (no split-K), 3 = fp32 split-K partial
#define ROWB 80
#define GBM 128
#define NSTG 4

template<int OUT>
__global__ __launch_bounds__(256, 2)
void mma_gemm(const __half* __restrict__ Ah, const __half* __restrict__ Bh,
              const float* __restrict__ bias,
              float* __restrict__ P, __half* __restrict__ Ch,
              int K, int Klen, int N, int ldc)
{
    constexpr int BHOFF = GBM * ROWB;
    constexpr int STG   = (GBM + 128) * ROWB;    // 20480

    extern __shared__ char smem[];
    const uint32_t sb = (uint32_t)__cvta_generic_to_shared(smem);

    const int tid  = threadIdx.x;
    const int wid  = tid >> 5, lane = tid & 31;
    const int wm   = (wid >> 2) * 64;
    const int wn   = (wid & 3) * 32;
    const int qrow = lane >> 2, qcol = lane & 3;
    const int m0   = blockIdx.y * GBM;
    const int n0   = blockIdx.x * 128;
    const int koff = blockIdx.z * Klen;

    const uint32_t aoff = (uint32_t)((wm + (lane & 15)) * ROWB + (lane >> 4) * 16);
    const uint32_t boff = (uint32_t)((wn + ((lane >> 4) << 3) + (lane & 7)) * ROWB
                                     + ((lane >> 3) & 1) * 16);

    float acc[4][4][4];
    #pragma unroll
    for (int i = 0; i < 4; i++)
        #pragma unroll
        for (int j = 0; j < 4; j++)
            #pragma unroll
            for (int q = 0; q < 4; q++) acc[i][j][q] = 0.f;

    auto load_stage = [&](int st, int kc) {
        const uint32_t base = sb + st * STG;
        #pragma unroll
        for (int i = 0; i < 2; i++) {
            int f = tid + i * 256;
            int row = f >> 2, c = f & 3;
            size_t g = (size_t)(m0 + row) * K + koff + kc + c * 8;
            cpasync16(base + (uint32_t)(row * ROWB + c * 16), Ah + g);
        }
        #pragma unroll
        for (int i = 0; i < 2; i++) {
            int f = tid + i * 256;
            int row = f >> 2, c = f & 3;
            size_t g = (size_t)(n0 + row) * K + koff + kc + c * 8;
            cpasync16(base + BHOFF + (uint32_t)(row * ROWB + c * 16), Bh + g);
        }
        asm volatile("cp.async.commit_group;\n" ::: "memory");
    };

    const int S = Klen >> 5;
    load_stage(0, 0);
    load_stage(1, 32);
    load_stage(2, 64);

    for (int s = 0; s < S; s++) {
        const int rem = S - s - 1;
        if (rem >= 2)      asm volatile("cp.async.wait_group 2;\n" ::: "memory");
        else if (rem == 1) asm volatile("cp.async.wait_group 1;\n" ::: "memory");
        else               asm volatile("cp.async.wait_group 0;\n" ::: "memory");
        __syncthreads();
        if (s + 3 < S) load_stage((s + 3) % NSTG, (s + 3) * 32);

        const uint32_t base = sb + (s % NSTG) * STG;
        #pragma unroll
        for (int ks = 0; ks < 2; ks++) {
            uint32_t bh[2][4];
            #pragma unroll
            for (int p = 0; p < 2; p++)
                ldsm4(bh[p], base + BHOFF + boff + p * (16*ROWB) + ks * 32);
            #pragma unroll
            for (int mt = 0; mt < 4; mt++) {
                uint32_t ah[4];
                ldsm4(ah, base + aoff + mt * (16*ROWB) + ks * 32);
                #pragma unroll
                for (int nt = 0; nt < 4; nt++) {
                    const uint32_t* bp = &bh[nt >> 1][(nt & 1) * 2];
                    mma16816(acc[mt][nt], ah, bp);
                }
            }
        }
        // no trailing sync: top-of-step sync two steps later protects reuse (depth >= 3)
    }

    if (OUT == 3) {
        float* Pz = P + (size_t)blockIdx.z * 1024 * N;
        #pragma unroll
        for (int mt = 0; mt < 4; mt++) {
            int r0 = m0 + wm + mt * 16 + qrow;
            #pragma unroll
            for (int nt = 0; nt < 4; nt++) {
                int c = n0 + wn + nt * 8 + qcol * 2;
                size_t i0 = (size_t)r0 * N + c;
                size_t i1 = (size_t)(r0 + 8) * N + c;
                Pz[i0] = acc[mt][nt][0]; Pz[i0 + 1] = acc[mt][nt][1];
                Pz[i1] = acc[mt][nt][2]; Pz[i1 + 1] = acc[mt][nt][3];
            }
        }
    } else {
        #pragma unroll
        for (int mt = 0; mt < 4; mt++) {
            int r0 = m0 + wm + mt * 16 + qrow;
            #pragma unroll
            for (int nt = 0; nt < 4; nt++) {
                int c = n0 + wn + nt * 8 + qcol * 2;
                float bv0 = bias[c], bv1 = bias[c + 1];
                float v00 = fmaxf(acc[mt][nt][0] + bv0, 0.f);
                float v01 = fmaxf(acc[mt][nt][1] + bv1, 0.f);
                float v10 = fmaxf(acc[mt][nt][2] + bv0, 0.f);
                float v11 = fmaxf(acc[mt][nt][3] + bv1, 0.f);
                size_t i0 = (size_t)r0 * ldc + c;
                size_t i1 = (size_t)(r0 + 8) * ldc + c;
                *(__half2*)(Ch + i0) = __halves2half2(__float2half_rn(v00), __float2half_rn(v01));
                *(__half2*)(Ch + i1) = __halves2half2(__float2half_rn(v10), __float2half_rn(v11));
            }
        }
    }
}

// ---------------- 3b) split-K reduce, NSLAB partial slabs (+bias) ----------------
// OUT: 0 = f32 to Cf, 2 = fp16 to Ch
template<int OUT, int NSLAB>
__global__ __launch_bounds__(256)
void reduce_k(const float* __restrict__ P, const float* __restrict__ bias,
              float* __restrict__ Cf, __half* __restrict__ Ch, int N, int ldc)
{
    const int idx = blockIdx.x * 256 + threadIdx.x;   // f4 index
    const int nq  = N >> 2;
    const int r   = idx / nq;
    const int c   = (idx % nq) * 4;
    const size_t p = (size_t)r * N + c;
    const size_t slab = (size_t)1024 * N;
    float4 a = *(const float4*)(P + p);
    float4 bv = *(const float4*)(bias + c);
    float v0 = a.x + bv.x, v1 = a.y + bv.y, v2 = a.z + bv.z, v3 = a.w + bv.w;
    #pragma unroll
    for (int zi = 1; zi < NSLAB; zi++) {
        float4 b = *(const float4*)(P + zi * slab + p);
        v0 += b.x; v1 += b.y; v2 += b.z; v3 += b.w;
    }
    if (OUT == 0) {
        *(float4*)(Cf + (size_t)r * ldc + c) = make_float4(v0, v1, v2, v3);
    } else {
        size_t o = (size_t)r * ldc + c;
        *(__half2*)(Ch + o)     = __halves2half2(__float2half_rn(v0), __float2half_rn(v1));
        *(__half2*)(Ch + o + 2) = __halves2half2(__float2half_rn(v2), __float2half_rn(v3));
    }
}

// ---------------- 4) bbox-size MLP layers 1+2 (parallel) ----------------
__global__ __launch_bounds__(256) void mlp12_kernel(
    const float* __restrict__ bboxes,
    const float* __restrict__ S1, const float* __restrict__ sb1,
    const float* __restrict__ S2, const float* __restrict__ sb2)
{
    __shared__ float e1[4][64];
    const int r0  = blockIdx.x * 4;
    const int tid = threadIdx.x;

    {
        const int row = tid >> 6, col = tid & 63;
        const float* bb = bboxes + (size_t)(r0 + row) * 4;
        float h = bb[3] - bb[1], w = bb[2] - bb[0];
        float v = h * S1[col] + w * S1[64 + col] + sb1[col];
        e1[row][col] = fmaxf(v, 0.f);
    }
    __syncthreads();

    float a[4];
    const float bv = sb2[tid];
    #pragma unroll
    for (int r = 0; r < 4; r++) a[r] = bv;
    #pragma unroll 8
    for (int k = 0; k < 64; k++) {
        const float s = S2[(size_t)k * 256 + tid];
        #pragma unroll
        for (int r = 0; r < 4; r++) a[r] += e1[r][k] * s;
    }
    #pragma unroll
    for (int r = 0; r < 4; r++)
        g_E2[(size_t)(r0 + r) * 256 + tid] = __float2half_rn(fmaxf(a[r], 0.f));
}

// ---------------- launch ----------------
extern "C" void kernel_launch(void* const* d_in, const int* in_sizes, int n_in,
                              void* d_out, int out_size)
{
    const float* z      = (const float*)d_in[0];
    const float* bboxes = (const float*)d_in[1];
    const float* W1     = (const float*)d_in[2];
    const float* b1     = (const float*)d_in[3];
    const float* W2     = (const float*)d_in[4];
    const float* b2     = (const float*)d_in[5];
    const float* S1     = (const float*)d_in[6];
    const float* sb1    = (const float*)d_in[7];
    const float* S2     = (const float*)d_in[8];
    const float* sb2    = (const float*)d_in[9];
    const float* S3     = (const float*)d_in[10];
    const float* sb3    = (const float*)d_in[11];
    const float* O      = (const float*)d_in[12];
    const float* ob     = (const float*)d_in[13];
    float* out = (float*)d_out;

    __half *X, *H, *CAT, *E2, *W1t, *W2t, *Ot, *S3t;
    float* P;
    cudaGetSymbolAddress((void**)&X,   g_X);
    cudaGetSymbolAddress((void**)&H,   g_H);
    cudaGetSymbolAddress((void**)&CAT, g_CAT);
    cudaGetSymbolAddress((void**)&E2,  g_E2);
    cudaGetSymbolAddress((void**)&W1t, g_W1t);
    cudaGetSymbolAddress((void**)&W2t, g_W2t);
    cudaGetSymbolAddress((void**)&Ot,  g_Ot);
    cudaGetSymbolAddress((void**)&S3t, g_S3t);
    cudaGetSymbolAddress((void**)&P,   g_P);

    constexpr int SMEM = (GBM + 128) * ROWB * NSTG;   // 81920

    static cudaStream_t s2 = nullptr;
    static cudaEvent_t  eFork = nullptr, eJoin = nullptr;
    static bool init_done = false;
    if (!init_done) {
        cudaFuncSetAttribute((const void*)mma_gemm<1>, cudaFuncAttributeMaxDynamicSharedMemorySize, SMEM);
        cudaFuncSetAttribute((const void*)mma_gemm<3>, cudaFuncAttributeMaxDynamicSharedMemorySize, SMEM);
        cudaStreamCreateWithFlags(&s2, cudaStreamNonBlocking);
        cudaEventCreateWithFlags(&eFork, cudaEventDisableTiming);
        cudaEventCreateWithFlags(&eJoin, cudaEventDisableTiming);
        init_done = true;
    }

    // ---- fork: independent preamble on s2 ----
    cudaEventRecord(eFork, 0);
    cudaStreamWaitEvent(s2, eFork, 0);
    // bbox-MLP path: layers 1+2, then layer 3 via tensor-core GEMM
    convt_kernel<<<dim3(1024/32, 256/32), dim3(32, 8), 0, s2>>>(S3, S3t, 256, 1024);
    mlp12_kernel<<<256, 256, 0, s2>>>(bboxes, S1, sb1, S2, sb2);
    mma_gemm<3><<<dim3(1024/128, 1024/128, 2), 256, SMEM, s2>>>(
        E2, S3t, nullptr, P + 4ul*1024*1024, nullptr, 256, 128, 1024, 0);
    reduce_k<2,2><<<1024, 256, 0, s2>>>(P + 4ul*1024*1024, sb3, nullptr, CAT + 1024, 1024, 2048);
    // weight conversions
    convt_kernel<<<dim3(5120/32, 1280/32), dim3(32, 8), 0, s2>>>(W1, W1t, 1280, 5120);
    convt_kernel<<<dim3(1024/32, 5120/32), dim3(32, 8), 0, s2>>>(W2, W2t, 5120, 1024);
    convt_kernel<<<dim3(1024/32, 2048/32), dim3(32, 8), 0, s2>>>(O,  Ot,  2048, 1024);
    cudaEventRecord(eJoin, s2);

    // ---- main stream: z transpose -> roi (monolithic, max parallelism) ----
    transpose_kernel<<<dim3(128, 20, 8), dim3(32, 8)>>>(z);
    roi_align_kernel<<<1024, 320>>>(bboxes);

    // ---- join before GEMMs ----
    cudaStreamWaitEvent(0, eJoin, 0);

    // GEMM1: H = relu(X @ W1 + b1), fused epilogue, no split-K (320 blocks)
    mma_gemm<1><<<dim3(5120/128, 1024/128), 256, SMEM>>>(
        X, W1t, b1, nullptr, H, 1280, 1280, 5120, 5120);

    // GEMM2: P = H @ W2 (split-K 4x1280) -> CAT[:, :1024] = fp16(sum+b2)
    mma_gemm<3><<<dim3(1024/128, 1024/128, 4), 256, SMEM>>>(
        H, W2t, nullptr, P, nullptr, 5120, 1280, 1024, 0);
    reduce_k<2,4><<<1024, 256>>>(P, b2, nullptr, CAT, 1024, 2048);

    // GEMM3: P = CAT @ O (split-K 4x512) -> out = sum+ob, f32
    mma_gemm<3><<<dim3(1024/128, 1024/128, 4), 256, SMEM>>>(
        CAT, Ot, nullptr, P, nullptr, 2048, 512, 1024, 0);
    reduce_k<0,4><<<1024, 256>>>(P, ob, out, nullptr, 1024, 1024);
}